// round 15
// baseline (speedup 1.0000x reference)
#include <cuda_runtime.h>
#include <cuda_bf16.h>
#include <math.h>
#include <stdint.h>

#define N 8192
#define D 256
#define NLAB 8
#define BT 64             // tile: 64x64
#define KA 512            // A row: [hi(256) | lo(256)]
#define CHUNK 64          // bf16 per chunk row = 128 bytes
#define NCHUNK 8          // chunk schedule: (hi_b,B_b),(lo_b,B_b) pairs
#define NTB (N / BT)      // 128 tile rows
#define NTRI (NTB * (NTB + 1) / 2)   // 8256 lower-triangular tiles
#define NSB 32            // sort blocks

// ---- device global scratch (no allocations allowed) ----
__device__ __nv_bfloat16 g_F[N * KA];   // sorted rows, [hi|lo]
__device__ int   g_pos[N];
__device__ int   g_lab_s[N];
__device__ int   g_spk_s[N];
__device__ float g_num[N];
__device__ float g_den[N];
__device__ int   g_bhist[NSB][NLAB];    // per-block label histograms
__device__ int   g_tiles[NTRI];         // packed live tiles (bi<<8)|bj
__device__ int   g_nlive;

// ---- dynamic smem layout (relative to 1024-aligned base) ----
#define SM_A0   0              // 4 A buffers: +k*8192
#define SM_B0   32768          // 4 B chunks resident: +b*8192
#define SM_LABC 65536
#define SM_SPKC 65792
#define SM_LABR 66048
#define SM_SPKR 66304
#define SM_END  66560
#define SMEM_DYN (SM_END + 1024)

// ------------------------------------------------------------------ PTX helpers
__device__ __forceinline__ uint32_t smem_u32(const void* p) {
    uint32_t a;
    asm("{ .reg .u64 t; cvta.to.shared.u64 t, %1; cvt.u32.u64 %0, t; }"
        : "=r"(a) : "l"(p));
    return a;
}
__device__ __forceinline__ void cp16(uint32_t dst, const void* src) {
    asm volatile("cp.async.cg.shared.global [%0], [%1], 16;"
                 :: "r"(dst), "l"(src) : "memory");
}
__device__ __forceinline__ void cp_commit() {
    asm volatile("cp.async.commit_group;" ::: "memory");
}
template <int NN>
__device__ __forceinline__ void cp_wait() {
    asm volatile("cp.async.wait_group %0;" :: "n"(NN) : "memory");
}
__device__ __forceinline__ void ldm_x4(uint32_t* r, uint32_t addr) {
    asm volatile("ldmatrix.sync.aligned.m8n8.x4.shared.b16 {%0,%1,%2,%3}, [%4];"
        : "=r"(r[0]), "=r"(r[1]), "=r"(r[2]), "=r"(r[3]) : "r"(addr));
}
__device__ __forceinline__ void mma_bf16(float* c, const uint32_t* a,
                                         uint32_t b0, uint32_t b1) {
    asm volatile(
        "mma.sync.aligned.m16n8k16.row.col.f32.bf16.bf16.f32 "
        "{%0,%1,%2,%3}, {%4,%5,%6,%7}, {%8,%9}, {%0,%1,%2,%3};"
        : "+f"(c[0]), "+f"(c[1]), "+f"(c[2]), "+f"(c[3])
        : "r"(a[0]), "r"(a[1]), "r"(a[2]), "r"(a[3]), "r"(b0), "r"(b1));
}

// ------------------------------------------------------------------
// Parallel counting-sort phase 1: per-block label histograms + zeroing.
__global__ void hist_kernel(const int* __restrict__ lab32) {
    const int tid = threadIdx.x;
    const int gi = blockIdx.x * 256 + tid;
    g_num[gi] = 0.f;
    g_den[gi] = 0.f;
    if (gi == 0) g_nlive = 0;

    __shared__ int cnt[NLAB];
    if (tid < NLAB) cnt[tid] = 0;
    int e = gi & 4095;
    int hiw = lab32[2 * e + 1];
    const int is64 = (__syncthreads_or(hiw) == 0);

    int l = is64 ? lab32[2 * gi] : lab32[gi];
    atomicAdd(&cnt[l], 1);
    __syncthreads();
    if (tid < NLAB) g_bhist[blockIdx.x][tid] = cnt[tid];
}

// ------------------------------------------------------------------
// Parallel counting-sort phase 2: stable rank + scatter + live-tile list.
__global__ void scatter_kernel(const int* __restrict__ lab32,
                               const int* __restrict__ spk32) {
    const int tid  = threadIdx.x;
    const int lane = tid & 31;
    const int w    = tid >> 5;
    const int gi   = blockIdx.x * 256 + tid;

    __shared__ int sh_hist[NLAB][NSB];
    __shared__ int sh_off[NLAB][NSB];
    __shared__ int sh_tot[NLAB];
    __shared__ int sh_bstart[NLAB];
    __shared__ int sh_wcnt[8][NLAB];

    sh_hist[tid >> 5][tid & 31] = g_bhist[tid & 31][tid >> 5];
    if (tid < 64) sh_wcnt[tid >> 3][tid & 7] = 0;
    __syncthreads();

    {
        int val = sh_hist[w][lane];
        int incl = val;
        #pragma unroll
        for (int o = 1; o < 32; o <<= 1) {
            int x = __shfl_up_sync(0xffffffffu, incl, o);
            if (lane >= o) incl += x;
        }
        sh_off[w][lane] = incl - val;
        if (lane == 31) sh_tot[w] = incl;
    }
    __syncthreads();
    if (tid == 0) {
        int run = 0;
        #pragma unroll
        for (int l = 0; l < NLAB; l++) { sh_bstart[l] = run; run += sh_tot[l]; }
    }

    int e = gi & 4095;
    int hiw = lab32[2 * e + 1];
    const int is64 = (__syncthreads_or(hiw) == 0);   // barrier: bstart visible

    int l = is64 ? lab32[2 * gi] : lab32[gi];
    int s = is64 ? spk32[2 * gi] : spk32[gi];

    unsigned m = __match_any_sync(0xffffffffu, l);
    unsigned lt = (1u << lane) - 1u;
    int laneRank = __popc(m & lt);
    if ((m & lt) == 0) sh_wcnt[w][l] = __popc(m);
    __syncthreads();

    int warpsBefore = 0;
    for (int ww = 0; ww < w; ww++) warpsBefore += sh_wcnt[ww][l];

    int p = sh_bstart[l] + sh_off[l][blockIdx.x] + warpsBefore + laneRank;
    g_pos[gi]  = p;
    g_lab_s[p] = l;
    g_spk_s[p] = s;

    // ---- live-tile worklist (liveness from bucket boundaries only) ----
    for (int tdx = gi; tdx < NTRI; tdx += NSB * 256) {
        int bi = (int)((sqrtf(8.0f * (float)tdx + 1.0f) - 1.0f) * 0.5f);
        while ((bi + 1) * (bi + 2) / 2 <= tdx) bi++;
        while (bi * (bi + 1) / 2 > tdx) bi--;
        int bj = tdx - bi * (bi + 1) / 2;
        int rs = bi * BT, cs = bj * BT;
        int l_rs = 0, l_re = 0, l_cs = 0, l_ce = 0;
        #pragma unroll
        for (int q = 1; q < NLAB; q++) {
            int bq = sh_bstart[q];
            if (bq <= rs) l_rs = q;
            if (bq <= rs + BT - 1) l_re = q;
            if (bq <= cs) l_cs = q;
            if (bq <= cs + BT - 1) l_ce = q;
        }
        if (l_cs <= l_re && l_ce >= l_rs) {
            int pos = atomicAdd(&g_nlive, 1);
            g_tiles[pos] = (bi << 8) | bj;
        }
    }
}

// ------------------------------------------------------------------
// L2-normalize, split into bf16 hi/lo, scatter to sorted position.
__global__ void gather_norm_kernel(const float* __restrict__ feat) {
    const int sub = threadIdx.x >> 6;
    const int row = blockIdx.x * 4 + sub;
    const int t = threadIdx.x & 63;
    float4 v = reinterpret_cast<const float4*>(feat + (size_t)row * D)[t];
    float ss = v.x * v.x + v.y * v.y + v.z * v.z + v.w * v.w;
    #pragma unroll
    for (int o = 16; o; o >>= 1) ss += __shfl_xor_sync(0xffffffffu, ss, o);
    __shared__ float sw[8];
    const int w = threadIdx.x >> 5;
    if ((threadIdx.x & 31) == 0) sw[w] = ss;
    __syncthreads();
    float inv = 1.f / fmaxf(sqrtf(sw[sub * 2] + sw[sub * 2 + 1]), 1e-12f);
    int p = g_pos[row];
    float c[4] = { v.x * inv, v.y * inv, v.z * inv, v.w * inv };
    __nv_bfloat16* F = g_F + (size_t)p * KA;
    __nv_bfloat16 hi4[4], lo4[4];
    #pragma unroll
    for (int j = 0; j < 4; j++) {
        hi4[j] = __float2bfloat16(c[j]);
        lo4[j] = __float2bfloat16(c[j] - __bfloat162float(hi4[j]));
    }
    *reinterpret_cast<uint2*>(F + 4 * t)       = *reinterpret_cast<uint2*>(hi4);
    *reinterpret_cast<uint2*>(F + 256 + 4 * t) = *reinterpret_cast<uint2*>(lo4);
}

// ------------------------------------------------------------------
// load one 64x64 bf16 chunk (128B rows), XOR-swizzled, via cp.async.
__device__ __forceinline__ void issue_one(uint32_t dst,
                                          const __nv_bfloat16* g, int t) {
    #pragma unroll
    for (int q = 0; q < 2; q++) {
        int u = t + q * 256;           // 0..511
        int row = u >> 3;              // 0..63
        int jj  = u & 7;
        uint32_t bo = row * 128 + jj * 16;
        uint32_t sw = bo ^ ((bo >> 3) & 0x70);
        cp16(dst + sw, g + (size_t)row * KA + jj * 8);
    }
}

// ------------------------------------------------------------------
// Worklist-dispatched 64x64 bf16-split mma.sync GEMM + symmetric epilogue.
// B (hi, 4 chunks, 32KB) resident; A in a 4-buffer distance-3 pipeline.
__global__ void __launch_bounds__(256, 3) mma_epilogue_kernel() {
    const int nlive = g_nlive;
    if ((int)blockIdx.x >= nlive) return;
    const int pk = g_tiles[blockIdx.x];
    const int bi = pk >> 8;
    const int bj = pk & 255;
    const int rs = bi * BT;
    const int cs = bj * BT;
    const bool diag = (bi == bj);

    extern __shared__ char smem_raw[];
    uint32_t sb_raw = smem_u32(smem_raw);
    uint32_t pad = ((sb_raw + 1023u) & ~1023u) - sb_raw;
    char* smem = smem_raw + pad;
    uint32_t sb = sb_raw + pad;

    const int t    = threadIdx.x;
    const int lane = t & 31;
    const int wid  = t >> 5;
    const int wm   = wid >> 2;     // 0..1 : 32-row slab
    const int wn   = wid & 3;      // 0..3 : 16-col slab

    if (t < BT) {
        ((int*)(smem + SM_LABC))[t] = g_lab_s[cs + t];
        ((int*)(smem + SM_SPKC))[t] = g_spk_s[cs + t];
        ((int*)(smem + SM_LABR))[t] = g_lab_s[rs + t];
        ((int*)(smem + SM_SPKR))[t] = g_spk_s[rs + t];
    }
    __syncthreads();

    const __nv_bfloat16* gA = g_F + (size_t)rs * KA;
    const __nv_bfloat16* gB = g_F + (size_t)cs * KA;   // hi half

    // A-chunk global index for pipeline chunk c: (c>>1) + (c&1)*4
    //   (hi block b at c=2b, lo block b at c=2b+1); B block = c>>1 resident.
    // prologue: 3 groups = chunk0(+all B), chunk1, chunk2
    issue_one(sb + SM_B0,         gB,             t);
    issue_one(sb + SM_B0 +  8192, gB +     CHUNK, t);
    issue_one(sb + SM_B0 + 16384, gB + 2 * CHUNK, t);
    issue_one(sb + SM_B0 + 24576, gB + 3 * CHUNK, t);
    issue_one(sb + SM_A0, gA, t);                       // chunk0 -> buf0
    cp_commit();
    issue_one(sb + SM_A0 + 8192, gA + 4 * CHUNK, t);    // chunk1 (lo0) -> buf1
    cp_commit();
    issue_one(sb + SM_A0 + 16384, gA + CHUNK, t);       // chunk2 (hi1) -> buf2
    cp_commit();

    float acc[2][2][4];
    #pragma unroll
    for (int mi = 0; mi < 2; mi++)
        #pragma unroll
        for (int ns = 0; ns < 2; ns++)
            #pragma unroll
            for (int r = 0; r < 4; r++) acc[mi][ns][r] = 0.f;

    const int mrow8 = ((lane >> 3) & 1) * 8 + (lane & 7);
    const int khalf = (lane >> 4) * 16;

    #pragma unroll
    for (int c = 0; c < NCHUNK; c++) {
        cp_wait<2>();      // chunk c's group (the (c+1)-th commit) has landed
        __syncthreads();   // all warps done reading buf (c-1)&3

        if (c + 3 < NCHUNK) {
            int cn = c + 3;
            int ca = (cn >> 1) + ((cn & 1) << 2);
            issue_one(sb + SM_A0 + (cn & 3) * 8192, gA + ca * CHUNK, t);
        }
        cp_commit();       // exactly one group per iteration (accounting)

        const uint32_t abase = sb + SM_A0 + (c & 3) * 8192;
        const uint32_t bbase = sb + SM_B0 + (c >> 1) * 8192;

        #pragma unroll
        for (int ks = 0; ks < 4; ks++) {
            const uint32_t kb = ks * 32 + khalf;
            uint32_t afr[2][4];
            #pragma unroll
            for (int mi = 0; mi < 2; mi++) {
                int row = wm * 32 + mi * 16 + mrow8;
                ldm_x4(afr[mi], abase + row * 128 + (kb ^ ((row & 7) << 4)));
            }
            uint32_t bfr[4];
            {
                int row = wn * 16 + mrow8;
                ldm_x4(bfr, bbase + row * 128 + (kb ^ ((row & 7) << 4)));
            }
            #pragma unroll
            for (int mi = 0; mi < 2; mi++) {
                mma_bf16(acc[mi][0], afr[mi], bfr[0], bfr[2]);
                mma_bf16(acc[mi][1], afr[mi], bfr[1], bfr[3]);
            }
        }
    }

    // ---- epilogue: masked exp + row AND (off-diag) column reduction ----
    const int* labc = (const int*)(smem + SM_LABC);
    const int* spkc = (const int*)(smem + SM_SPKC);
    const int* labr = (const int*)(smem + SM_LABR);
    const int* spkr = (const int*)(smem + SM_SPKR);
    const float invT = 1.25f;

    int clab[2][2], cspk[2][2], ccol[2][2];
    float colnum[2][2], colden[2][2];
    #pragma unroll
    for (int ns = 0; ns < 2; ns++)
        #pragma unroll
        for (int j = 0; j < 2; j++) {
            int col = wn * 16 + ns * 8 + (lane & 3) * 2 + j;
            ccol[ns][j] = col;
            clab[ns][j] = labc[col];
            cspk[ns][j] = spkc[col];
            colnum[ns][j] = 0.f;
            colden[ns][j] = 0.f;
        }

    #pragma unroll
    for (int mi = 0; mi < 2; mi++) {
        #pragma unroll
        for (int half = 0; half < 2; half++) {
            int row = wm * 32 + mi * 16 + (lane >> 2) + half * 8;
            int gi = rs + row;
            int li = labr[row];
            int si = spkr[row];
            float num = 0.f, den = 0.f;
            #pragma unroll
            for (int ns = 0; ns < 2; ns++)
                #pragma unroll
                for (int j = 0; j < 2; j++) {
                    if (clab[ns][j] == li && gi != cs + ccol[ns][j]) {
                        float e = __expf(acc[mi][ns][j + 2 * half] * invT);
                        den += e;
                        colden[ns][j] += e;
                        if (cspk[ns][j] == si) {
                            num += e;
                            colnum[ns][j] += e;
                        }
                    }
                }
            num += __shfl_xor_sync(0xffffffffu, num, 1);
            num += __shfl_xor_sync(0xffffffffu, num, 2);
            den += __shfl_xor_sync(0xffffffffu, den, 1);
            den += __shfl_xor_sync(0xffffffffu, den, 2);
            if ((lane & 3) == 0) {
                if (num != 0.f) atomicAdd(&g_num[gi], num);
                if (den != 0.f) atomicAdd(&g_den[gi], den);
            }
        }
    }

    if (!diag) {
        #pragma unroll
        for (int ns = 0; ns < 2; ns++)
            #pragma unroll
            for (int j = 0; j < 2; j++) {
                float cn = colnum[ns][j];
                float cd = colden[ns][j];
                cn += __shfl_xor_sync(0xffffffffu, cn, 4);
                cn += __shfl_xor_sync(0xffffffffu, cn, 8);
                cn += __shfl_xor_sync(0xffffffffu, cn, 16);
                cd += __shfl_xor_sync(0xffffffffu, cd, 4);
                cd += __shfl_xor_sync(0xffffffffu, cd, 8);
                cd += __shfl_xor_sync(0xffffffffu, cd, 16);
                if (lane < 4) {
                    int gj = cs + ccol[ns][j];
                    if (cn != 0.f) atomicAdd(&g_num[gj], cn);
                    if (cd != 0.f) atomicAdd(&g_den[gj], cd);
                }
            }
    }
}

// ------------------------------------------------------------------
// single-block fused finalize + output write
__global__ void finalize_kernel(float* out) {
    const int t = threadIdx.x;  // 1024 threads
    float nums[8], dens[8];
    #pragma unroll
    for (int j = 0; j < 8; j++) {
        int i = t + j * 1024;
        nums[j] = g_num[i];
        dens[j] = g_den[i];
    }
    float loss = 0.f;
    int c = 0;
    #pragma unroll
    for (int j = 0; j < 8; j++) {
        if (nums[j] > 0.f) {
            loss += __logf(dens[j] + 1e-7f) - __logf(nums[j]);
            c++;
        }
    }
    #pragma unroll
    for (int o = 16; o; o >>= 1) {
        loss += __shfl_xor_sync(0xffffffffu, loss, o);
        c    += __shfl_xor_sync(0xffffffffu, c, o);
    }
    __shared__ float sl[32];
    __shared__ int   sc[32];
    int lane = t & 31, w = t >> 5;
    if (lane == 0) { sl[w] = loss; sc[w] = c; }
    __syncthreads();
    if (t == 0) {
        float tl = 0.f; int tc = 0;
        #pragma unroll
        for (int q = 0; q < 32; q++) { tl += sl[q]; tc += sc[q]; }
        out[0] = (tc > 0) ? tl / (float)tc : 0.f;
    }
}

// ------------------------------------------------------------------
extern "C" void kernel_launch(void* const* d_in, const int* in_sizes, int n_in,
                              void* d_out, int out_size) {
    const float* feat = (const float*)d_in[0];
    const int*   lab  = (const int*)d_in[1];
    const int*   spk  = (const int*)d_in[2];
    float* out = (float*)d_out;

    cudaFuncSetAttribute(mma_epilogue_kernel,
                         cudaFuncAttributeMaxDynamicSharedMemorySize, SMEM_DYN);

    hist_kernel<<<NSB, 256>>>(lab);
    scatter_kernel<<<NSB, 256>>>(lab, spk);
    gather_norm_kernel<<<N / 4, 256>>>(feat);
    mma_epilogue_kernel<<<NTRI, 256, SMEM_DYN>>>();
    finalize_kernel<<<1, 1024>>>(out);
}

// round 16
// speedup vs baseline: 1.0577x; 1.0577x over previous
#include <cuda_runtime.h>
#include <cuda_bf16.h>
#include <math.h>
#include <stdint.h>

#define N 8192
#define D 256
#define NLAB 8
#define BT 64             // tile: 64x64
#define KA 512            // A row: [hi(256) | lo(256)]
#define CHUNK 64          // bf16 per chunk row = 128 bytes
#define NCHUNK 8          // chunk schedule: (hi_b,B_b),(lo_b,B_b) pairs
#define NTB (N / BT)      // 128 tile rows
#define NTRI (NTB * (NTB + 1) / 2)   // 8256 lower-triangular tiles
#define NSB 32            // sort blocks

// ---- device global scratch (no allocations allowed) ----
__device__ __nv_bfloat16 g_F[N * KA];   // sorted rows, [hi|lo]
__device__ int   g_pos[N];
__device__ int   g_lab_s[N];
__device__ int   g_spk_s[N];
__device__ float g_num[N];
__device__ float g_den[N];
__device__ int   g_bhist[NSB][NLAB];    // per-block label histograms
__device__ int   g_tiles[NTRI];         // packed live tiles (bi<<8)|bj
__device__ int   g_nlive;

// ---- dynamic smem layout (relative to 1024-aligned base) ----
#define SM_A0   0              // 3 A buffers: +k*8192
#define SM_B0   24576          // 3 B buffers: +k*8192 (B blocks 0,1,2,3 -> 0,1,2,0)
#define SM_LABC 49152
#define SM_SPKC 49408
#define SM_LABR 49664
#define SM_SPKR 49920
#define SM_END  50176
#define SMEM_DYN (SM_END + 1024)

// ------------------------------------------------------------------ PTX helpers
__device__ __forceinline__ uint32_t smem_u32(const void* p) {
    uint32_t a;
    asm("{ .reg .u64 t; cvta.to.shared.u64 t, %1; cvt.u32.u64 %0, t; }"
        : "=r"(a) : "l"(p));
    return a;
}
__device__ __forceinline__ void cp16(uint32_t dst, const void* src) {
    asm volatile("cp.async.cg.shared.global [%0], [%1], 16;"
                 :: "r"(dst), "l"(src) : "memory");
}
__device__ __forceinline__ void cp_commit() {
    asm volatile("cp.async.commit_group;" ::: "memory");
}
template <int NN>
__device__ __forceinline__ void cp_wait() {
    asm volatile("cp.async.wait_group %0;" :: "n"(NN) : "memory");
}
__device__ __forceinline__ void ldm_x4(uint32_t* r, uint32_t addr) {
    asm volatile("ldmatrix.sync.aligned.m8n8.x4.shared.b16 {%0,%1,%2,%3}, [%4];"
        : "=r"(r[0]), "=r"(r[1]), "=r"(r[2]), "=r"(r[3]) : "r"(addr));
}
__device__ __forceinline__ void mma_bf16(float* c, const uint32_t* a,
                                         uint32_t b0, uint32_t b1) {
    asm volatile(
        "mma.sync.aligned.m16n8k16.row.col.f32.bf16.bf16.f32 "
        "{%0,%1,%2,%3}, {%4,%5,%6,%7}, {%8,%9}, {%0,%1,%2,%3};"
        : "+f"(c[0]), "+f"(c[1]), "+f"(c[2]), "+f"(c[3])
        : "r"(a[0]), "r"(a[1]), "r"(a[2]), "r"(a[3]), "r"(b0), "r"(b1));
}

// ------------------------------------------------------------------
// Parallel counting-sort phase 1: per-block label histograms + zeroing.
__global__ void hist_kernel(const int* __restrict__ lab32) {
    const int tid = threadIdx.x;
    const int gi = blockIdx.x * 256 + tid;
    g_num[gi] = 0.f;
    g_den[gi] = 0.f;
    if (gi == 0) g_nlive = 0;

    __shared__ int cnt[NLAB];
    if (tid < NLAB) cnt[tid] = 0;
    int e = gi & 4095;
    int hiw = lab32[2 * e + 1];
    const int is64 = (__syncthreads_or(hiw) == 0);

    int l = is64 ? lab32[2 * gi] : lab32[gi];
    atomicAdd(&cnt[l], 1);
    __syncthreads();
    if (tid < NLAB) g_bhist[blockIdx.x][tid] = cnt[tid];
}

// ------------------------------------------------------------------
// Parallel counting-sort phase 2: stable rank + scatter + live-tile list.
__global__ void scatter_kernel(const int* __restrict__ lab32,
                               const int* __restrict__ spk32) {
    const int tid  = threadIdx.x;
    const int lane = tid & 31;
    const int w    = tid >> 5;
    const int gi   = blockIdx.x * 256 + tid;

    __shared__ int sh_hist[NLAB][NSB];
    __shared__ int sh_off[NLAB][NSB];
    __shared__ int sh_tot[NLAB];
    __shared__ int sh_bstart[NLAB];
    __shared__ int sh_wcnt[8][NLAB];

    sh_hist[tid >> 5][tid & 31] = g_bhist[tid & 31][tid >> 5];
    if (tid < 64) sh_wcnt[tid >> 3][tid & 7] = 0;
    __syncthreads();

    {
        int val = sh_hist[w][lane];
        int incl = val;
        #pragma unroll
        for (int o = 1; o < 32; o <<= 1) {
            int x = __shfl_up_sync(0xffffffffu, incl, o);
            if (lane >= o) incl += x;
        }
        sh_off[w][lane] = incl - val;
        if (lane == 31) sh_tot[w] = incl;
    }
    __syncthreads();
    if (tid == 0) {
        int run = 0;
        #pragma unroll
        for (int l = 0; l < NLAB; l++) { sh_bstart[l] = run; run += sh_tot[l]; }
    }

    int e = gi & 4095;
    int hiw = lab32[2 * e + 1];
    const int is64 = (__syncthreads_or(hiw) == 0);   // barrier: bstart visible

    int l = is64 ? lab32[2 * gi] : lab32[gi];
    int s = is64 ? spk32[2 * gi] : spk32[gi];

    unsigned m = __match_any_sync(0xffffffffu, l);
    unsigned lt = (1u << lane) - 1u;
    int laneRank = __popc(m & lt);
    if ((m & lt) == 0) sh_wcnt[w][l] = __popc(m);
    __syncthreads();

    int warpsBefore = 0;
    for (int ww = 0; ww < w; ww++) warpsBefore += sh_wcnt[ww][l];

    int p = sh_bstart[l] + sh_off[l][blockIdx.x] + warpsBefore + laneRank;
    g_pos[gi]  = p;
    g_lab_s[p] = l;
    g_spk_s[p] = s;

    // ---- live-tile worklist (liveness from bucket boundaries only) ----
    for (int tdx = gi; tdx < NTRI; tdx += NSB * 256) {
        int bi = (int)((sqrtf(8.0f * (float)tdx + 1.0f) - 1.0f) * 0.5f);
        while ((bi + 1) * (bi + 2) / 2 <= tdx) bi++;
        while (bi * (bi + 1) / 2 > tdx) bi--;
        int bj = tdx - bi * (bi + 1) / 2;
        int rs = bi * BT, cs = bj * BT;
        int l_rs = 0, l_re = 0, l_cs = 0, l_ce = 0;
        #pragma unroll
        for (int q = 1; q < NLAB; q++) {
            int bq = sh_bstart[q];
            if (bq <= rs) l_rs = q;
            if (bq <= rs + BT - 1) l_re = q;
            if (bq <= cs) l_cs = q;
            if (bq <= cs + BT - 1) l_ce = q;
        }
        if (l_cs <= l_re && l_ce >= l_rs) {
            int pos = atomicAdd(&g_nlive, 1);
            g_tiles[pos] = (bi << 8) | bj;
        }
    }
}

// ------------------------------------------------------------------
// L2-normalize, split into bf16 hi/lo, scatter to sorted position.
__global__ void gather_norm_kernel(const float* __restrict__ feat) {
    const int sub = threadIdx.x >> 6;
    const int row = blockIdx.x * 4 + sub;
    const int t = threadIdx.x & 63;
    float4 v = reinterpret_cast<const float4*>(feat + (size_t)row * D)[t];
    float ss = v.x * v.x + v.y * v.y + v.z * v.z + v.w * v.w;
    #pragma unroll
    for (int o = 16; o; o >>= 1) ss += __shfl_xor_sync(0xffffffffu, ss, o);
    __shared__ float sw[8];
    const int w = threadIdx.x >> 5;
    if ((threadIdx.x & 31) == 0) sw[w] = ss;
    __syncthreads();
    float inv = 1.f / fmaxf(sqrtf(sw[sub * 2] + sw[sub * 2 + 1]), 1e-12f);
    int p = g_pos[row];
    float c[4] = { v.x * inv, v.y * inv, v.z * inv, v.w * inv };
    __nv_bfloat16* F = g_F + (size_t)p * KA;
    __nv_bfloat16 hi4[4], lo4[4];
    #pragma unroll
    for (int j = 0; j < 4; j++) {
        hi4[j] = __float2bfloat16(c[j]);
        lo4[j] = __float2bfloat16(c[j] - __bfloat162float(hi4[j]));
    }
    *reinterpret_cast<uint2*>(F + 4 * t)       = *reinterpret_cast<uint2*>(hi4);
    *reinterpret_cast<uint2*>(F + 256 + 4 * t) = *reinterpret_cast<uint2*>(lo4);
}

// ------------------------------------------------------------------
// load one 64x64 bf16 chunk (128B rows), XOR-swizzled, via cp.async.
__device__ __forceinline__ void issue_one(uint32_t dst,
                                          const __nv_bfloat16* g, int t) {
    #pragma unroll
    for (int q = 0; q < 2; q++) {
        int u = t + q * 256;           // 0..511
        int row = u >> 3;              // 0..63
        int jj  = u & 7;
        uint32_t bo = row * 128 + jj * 16;
        uint32_t sw = bo ^ ((bo >> 3) & 0x70);
        cp16(dst + sw, g + (size_t)row * KA + jj * 8);
    }
}

// ------------------------------------------------------------------
// Worklist-dispatched 64x64 bf16-split mma.sync GEMM + symmetric epilogue.
// 3 A buffers (distance-2 pipeline) + 3 B buffers (B3 reuses buf0). occ 4.
// chunk c: A-chunk (c>>1)+(c&1)*4 in Abuf[c%3]; B block c>>1 in Bbuf[bmap].
__global__ void __launch_bounds__(256, 4) mma_epilogue_kernel() {
    const int nlive = g_nlive;
    if ((int)blockIdx.x >= nlive) return;
    const int pk = g_tiles[blockIdx.x];
    const int bi = pk >> 8;
    const int bj = pk & 255;
    const int rs = bi * BT;
    const int cs = bj * BT;
    const bool diag = (bi == bj);

    extern __shared__ char smem_raw[];
    uint32_t sb_raw = smem_u32(smem_raw);
    uint32_t pad = ((sb_raw + 1023u) & ~1023u) - sb_raw;
    char* smem = smem_raw + pad;
    uint32_t sb = sb_raw + pad;

    const int t    = threadIdx.x;
    const int lane = t & 31;
    const int wid  = t >> 5;
    const int wm   = wid >> 2;     // 0..1 : 32-row slab
    const int wn   = wid & 3;      // 0..3 : 16-col slab

    if (t < BT) {
        ((int*)(smem + SM_LABC))[t] = g_lab_s[cs + t];
        ((int*)(smem + SM_SPKC))[t] = g_spk_s[cs + t];
        ((int*)(smem + SM_LABR))[t] = g_lab_s[rs + t];
        ((int*)(smem + SM_SPKR))[t] = g_spk_s[rs + t];
    }
    __syncthreads();

    const __nv_bfloat16* gA = g_F + (size_t)rs * KA;
    const __nv_bfloat16* gB = g_F + (size_t)cs * KA;   // hi half

    // prologue: G0 = {B0,B1,B2, A-chunk0}; G1 = {A-chunk1 (lo0)}
    issue_one(sb + SM_B0,         gB,             t);
    issue_one(sb + SM_B0 +  8192, gB +     CHUNK, t);
    issue_one(sb + SM_B0 + 16384, gB + 2 * CHUNK, t);
    issue_one(sb + SM_A0,         gA,             t);
    cp_commit();
    issue_one(sb + SM_A0 + 8192,  gA + 4 * CHUNK, t);
    cp_commit();

    float acc[2][2][4];
    #pragma unroll
    for (int mi = 0; mi < 2; mi++)
        #pragma unroll
        for (int ns = 0; ns < 2; ns++)
            #pragma unroll
            for (int r = 0; r < 4; r++) acc[mi][ns][r] = 0.f;

    const int mrow8 = ((lane >> 3) & 1) * 8 + (lane & 7);
    const int khalf = (lane >> 4) * 16;
    const int bmap[4] = {0, 1, 2, 0};   // B block -> B buffer

    #pragma unroll
    for (int c = 0; c < NCHUNK; c++) {
        cp_wait<1>();      // group G_c (chunk c's load) has landed
        __syncthreads();   // all warps done reading Abuf[(c+2)%3] (chunk c-1)

        if (c + 2 < NCHUNK) {
            int cn = c + 2;
            int ca = (cn >> 1) + ((cn & 1) << 2);
            issue_one(sb + SM_A0 + (cn % 3) * 8192, gA + ca * CHUNK, t);
            if (c == 4)    // B3 -> Bbuf0 (B0 reads retired at iter 2's barrier)
                issue_one(sb + SM_B0, gB + 3 * CHUNK, t);
        }
        cp_commit();       // exactly one group per iteration (accounting)

        const uint32_t abase = sb + SM_A0 + (c % 3) * 8192;
        const uint32_t bbase = sb + SM_B0 + bmap[c >> 1] * 8192;

        #pragma unroll
        for (int ks = 0; ks < 4; ks++) {
            const uint32_t kb = ks * 32 + khalf;
            uint32_t afr[2][4];
            #pragma unroll
            for (int mi = 0; mi < 2; mi++) {
                int row = wm * 32 + mi * 16 + mrow8;
                ldm_x4(afr[mi], abase + row * 128 + (kb ^ ((row & 7) << 4)));
            }
            uint32_t bfr[4];
            {
                int row = wn * 16 + mrow8;
                ldm_x4(bfr, bbase + row * 128 + (kb ^ ((row & 7) << 4)));
            }
            #pragma unroll
            for (int mi = 0; mi < 2; mi++) {
                mma_bf16(acc[mi][0], afr[mi], bfr[0], bfr[2]);
                mma_bf16(acc[mi][1], afr[mi], bfr[1], bfr[3]);
            }
        }
    }

    // ---- epilogue: masked exp + row AND (off-diag) column reduction ----
    const int* labc = (const int*)(smem + SM_LABC);
    const int* spkc = (const int*)(smem + SM_SPKC);
    const int* labr = (const int*)(smem + SM_LABR);
    const int* spkr = (const int*)(smem + SM_SPKR);
    const float invT = 1.25f;

    int clab[2][2], cspk[2][2], ccol[2][2];
    float colnum[2][2], colden[2][2];
    #pragma unroll
    for (int ns = 0; ns < 2; ns++)
        #pragma unroll
        for (int j = 0; j < 2; j++) {
            int col = wn * 16 + ns * 8 + (lane & 3) * 2 + j;
            ccol[ns][j] = col;
            clab[ns][j] = labc[col];
            cspk[ns][j] = spkc[col];
            colnum[ns][j] = 0.f;
            colden[ns][j] = 0.f;
        }

    #pragma unroll
    for (int mi = 0; mi < 2; mi++) {
        #pragma unroll
        for (int half = 0; half < 2; half++) {
            int row = wm * 32 + mi * 16 + (lane >> 2) + half * 8;
            int gi = rs + row;
            int li = labr[row];
            int si = spkr[row];
            float num = 0.f, den = 0.f;
            #pragma unroll
            for (int ns = 0; ns < 2; ns++)
                #pragma unroll
                for (int j = 0; j < 2; j++) {
                    if (clab[ns][j] == li && gi != cs + ccol[ns][j]) {
                        float e = __expf(acc[mi][ns][j + 2 * half] * invT);
                        den += e;
                        colden[ns][j] += e;
                        if (cspk[ns][j] == si) {
                            num += e;
                            colnum[ns][j] += e;
                        }
                    }
                }
            num += __shfl_xor_sync(0xffffffffu, num, 1);
            num += __shfl_xor_sync(0xffffffffu, num, 2);
            den += __shfl_xor_sync(0xffffffffu, den, 1);
            den += __shfl_xor_sync(0xffffffffu, den, 2);
            if ((lane & 3) == 0) {
                if (num != 0.f) atomicAdd(&g_num[gi], num);
                if (den != 0.f) atomicAdd(&g_den[gi], den);
            }
        }
    }

    if (!diag) {
        #pragma unroll
        for (int ns = 0; ns < 2; ns++)
            #pragma unroll
            for (int j = 0; j < 2; j++) {
                float cn = colnum[ns][j];
                float cd = colden[ns][j];
                cn += __shfl_xor_sync(0xffffffffu, cn, 4);
                cn += __shfl_xor_sync(0xffffffffu, cn, 8);
                cn += __shfl_xor_sync(0xffffffffu, cn, 16);
                cd += __shfl_xor_sync(0xffffffffu, cd, 4);
                cd += __shfl_xor_sync(0xffffffffu, cd, 8);
                cd += __shfl_xor_sync(0xffffffffu, cd, 16);
                if (lane < 4) {
                    int gj = cs + ccol[ns][j];
                    if (cn != 0.f) atomicAdd(&g_num[gj], cn);
                    if (cd != 0.f) atomicAdd(&g_den[gj], cd);
                }
            }
    }
}

// ------------------------------------------------------------------
// single-block fused finalize + output write
__global__ void finalize_kernel(float* out) {
    const int t = threadIdx.x;  // 1024 threads
    float nums[8], dens[8];
    #pragma unroll
    for (int j = 0; j < 8; j++) {
        int i = t + j * 1024;
        nums[j] = g_num[i];
        dens[j] = g_den[i];
    }
    float loss = 0.f;
    int c = 0;
    #pragma unroll
    for (int j = 0; j < 8; j++) {
        if (nums[j] > 0.f) {
            loss += __logf(dens[j] + 1e-7f) - __logf(nums[j]);
            c++;
        }
    }
    #pragma unroll
    for (int o = 16; o; o >>= 1) {
        loss += __shfl_xor_sync(0xffffffffu, loss, o);
        c    += __shfl_xor_sync(0xffffffffu, c, o);
    }
    __shared__ float sl[32];
    __shared__ int   sc[32];
    int lane = t & 31, w = t >> 5;
    if (lane == 0) { sl[w] = loss; sc[w] = c; }
    __syncthreads();
    if (t == 0) {
        float tl = 0.f; int tc = 0;
        #pragma unroll
        for (int q = 0; q < 32; q++) { tl += sl[q]; tc += sc[q]; }
        out[0] = (tc > 0) ? tl / (float)tc : 0.f;
    }
}

// ------------------------------------------------------------------
extern "C" void kernel_launch(void* const* d_in, const int* in_sizes, int n_in,
                              void* d_out, int out_size) {
    const float* feat = (const float*)d_in[0];
    const int*   lab  = (const int*)d_in[1];
    const int*   spk  = (const int*)d_in[2];
    float* out = (float*)d_out;

    cudaFuncSetAttribute(mma_epilogue_kernel,
                         cudaFuncAttributeMaxDynamicSharedMemorySize, SMEM_DYN);

    hist_kernel<<<NSB, 256>>>(lab);
    scatter_kernel<<<NSB, 256>>>(lab, spk);
    gather_norm_kernel<<<N / 4, 256>>>(feat);
    mma_epilogue_kernel<<<NTRI, 256, SMEM_DYN>>>();
    finalize_kernel<<<1, 1024>>>(out);
}